// round 12
// baseline (speedup 1.0000x reference)
#include <cuda_runtime.h>
#include <cstdint>

// Rotation42d: per-sample rotation of (256, 3, 224, 224) fp32 by label in {0,1,2,3}.
// Per sample: 49 blocks x 256 threads, 3 channels fused (shared label, MLP=3).
// R11 experiment: cap residency at 4 CTAs/SM (50% occ) to cut cross-CTA
// L1tex wavefront-queue contention and store-stream interleaving while
// keeping ~49KB/SM in flight (>= latency-hiding floor ~10-19KB).
//   - lab 0/2: linear 4KB-contiguous chunk copy per channel plane.
//   - lab 1/3: 32x32 padded smem tile transpose, coalesced both sides.
// All global traffic 128-bit with streaming cache hints.

#define HW 224
#define TILES 7          // 224/32
#define ROW4 56          // 224/4 float4 per row
#define CH_STRIDE (HW * ROW4)   // float4 per channel plane = 12544 (= 49*256)

__global__ __launch_bounds__(256, 4) void rot_kernel(
    const float4* __restrict__ x4,
    const int*    __restrict__ label,
    float4*       __restrict__ out4,
    float*        __restrict__ out_tail,   // may be null
    int                         n_tail)
{
    const int b   = blockIdx.z;          // sample 0..255
    const int lab = __ldg(label + b) & 3;

    const int bx = blockIdx.x;           // tile col (transpose) / chunk low
    const int by = blockIdx.y;           // tile row (transpose) / chunk high
    const int tx = threadIdx.x;          // 0..7
    const int ty = threadIdx.y;          // 0..31

    if (out_tail != nullptr &&
        (bx | by | tx | ty) == 0 && b < n_tail) {
        out_tail[b] = (float)__ldg(label + b);
    }

    const float4* __restrict__ in = x4   + (size_t)b * (3 * CH_STRIDE);
    float4* __restrict__       o  = out4 + (size_t)b * (3 * CH_STRIDE);

    __shared__ float tile[3][32][33];    // +1 pad: conflict-free transposed reads

    if (lab == 0 || lab == 2) {
        // Linear chunk remap: block t copies float4 [t*256, t*256+256) of each
        // plane. Contiguous 4KB per block per channel.
        const int t   = by * TILES + bx;            // 0..48
        const int idx = t * 256 + (ty * 8 + tx);    // dst float4 index in plane
        int src;
        if (lab == 0) {
            src = idx;
        } else {
            const int h = idx / ROW4;               // dst row
            const int g = idx - h * ROW4;           // dst col group
            src = (HW - 1 - h) * ROW4 + g;          // flipped row, same cols
        }
        const float4 v0 = __ldcs(in + src);
        const float4 v1 = __ldcs(in + CH_STRIDE + src);
        const float4 v2 = __ldcs(in + 2 * CH_STRIDE + src);
        __stcs(o + idx, v0);
        __stcs(o + CH_STRIDE + idx, v1);
        __stcs(o + 2 * CH_STRIDE + idx, v2);
    } else {
        // r90 : out[h][w] = in[w][h]       -> tile[r][c] = in[bx*32+r][by*32+c]
        // r270: out[h][w] = in[HW-1-w][h]  -> tile[r][c] = in[HW-1-(bx*32+r)][by*32+c]
        const int r = ty;
        const int src_row = (lab == 1) ? (bx * 32 + r)
                                       : (HW - 1 - (bx * 32 + r));
        const int sidx = src_row * ROW4 + (by * 8 + tx);
        const float4 v0 = __ldcs(in + sidx);
        const float4 v1 = __ldcs(in + CH_STRIDE + sidx);
        const float4 v2 = __ldcs(in + 2 * CH_STRIDE + sidx);
        #pragma unroll
        for (int k = 0; k < 4; k++) {
            tile[0][r][4 * tx + k] = ((const float*)&v0)[k];
            tile[1][r][4 * tx + k] = ((const float*)&v1)[k];
            tile[2][r][4 * tx + k] = ((const float*)&v2)[k];
        }
        __syncthreads();

        const int i = ty;
        const int g = tx;
        const int dst = (by * 32 + i) * ROW4 + (bx * 8 + g);
        #pragma unroll
        for (int ch = 0; ch < 3; ch++) {
            float4 w;
            w.x = tile[ch][4 * g + 0][i];
            w.y = tile[ch][4 * g + 1][i];
            w.z = tile[ch][4 * g + 2][i];
            w.w = tile[ch][4 * g + 3][i];
            __stcs(o + ch * CH_STRIDE + dst, w);
        }
    }
}

extern "C" void kernel_launch(void* const* d_in, const int* in_sizes, int n_in,
                              void* d_out, int out_size)
{
    const float4* x     = (const float4*)d_in[0];
    const int*    label = (const int*)d_in[1];
    float4*       out   = (float4*)d_out;

    const int  n_label   = (n_in > 1) ? in_sizes[1] : 256;
    const long img_elems = 256L * 3L * HW * HW;  // 38,535,168

    float* out_tail = nullptr;
    int    n_tail   = 0;
    if ((long)out_size > img_elems) {
        const int tail = (int)((long)out_size - img_elems);
        n_tail   = tail < n_label ? tail : n_label;
        out_tail = (float*)d_out + img_elems;
    }

    dim3 grid(TILES, TILES, 256);
    dim3 block(8, 32);
    rot_kernel<<<grid, block>>>(x, label, out, out_tail, n_tail);
}